// round 14
// baseline (speedup 1.0000x reference)
#include <cuda_runtime.h>
#include <cstdint>

#define BLOCK 256
#define ROWS  1024           // rows per tile; 5120 input floats = 1280 float4
#define NBLOCKS 740          // 148 SMs * 5 blocks (40KB static smem each)

__device__ float g_partials[NBLOCKS];
__device__ unsigned int g_count = 0;

__device__ __forceinline__ void cp16(uint32_t smem_addr, const void* gptr) {
    asm volatile("cp.async.cg.shared.global [%0], [%1], 16;"
                 :: "r"(smem_addr), "l"(gptr));
}
__device__ __forceinline__ void cp_commit() {
    asm volatile("cp.async.commit_group;");
}
template <int N>
__device__ __forceinline__ void cp_wait() {
    asm volatile("cp.async.wait_group %0;" :: "n"(N));
}

__global__ void __launch_bounds__(BLOCK)
loss_kernel(const float* __restrict__ in,
            const float* __restrict__ tgt,
            long long nrows,
            float* __restrict__ out)
{
    __shared__ __align__(16) float s_in[2][ROWS * 5];   // 40960 bytes
    __shared__ float s_red[BLOCK / 32];

    const int tid = threadIdx.x;
    const long long fulltiles = nrows / ROWS;
    const long long step = gridDim.x;
    float acc = 0.0f;

    // Tail rows (nrows % ROWS) handled directly by block 0.
    if (blockIdx.x == 0) {
        for (long long r = fulltiles * ROWS + tid; r < nrows; r += BLOCK) {
            const float x0 = in[r * 5 + 0];
            const float x2 = in[r * 5 + 2];
            const float x4 = in[r * 5 + 4];
            const float t  = tgt[r];
            const float d  = (fabsf(x4 - x2) < 0.1f) ? (x0 - x4) : (x0 - t);
            acc += fabsf(d);
        }
    }

    // Stage only the inputs tile via cp.async (targets read directly, coalesced).
    auto stage = [&](int buf, long long tile) {
        if (tile < fulltiles) {
            const float* src = in + tile * (long long)ROWS * 5;
            const uint32_t sbase = (uint32_t)__cvta_generic_to_shared(&s_in[buf][0]);
            #pragma unroll
            for (int i = 0; i < 5; i++)
                cp16(sbase + (uint32_t)(tid + i * BLOCK) * 16,
                     src + (size_t)(tid + i * BLOCK) * 4);
        }
        cp_commit();
    };

    const long long t0 = blockIdx.x;
    stage(0, t0);
    stage(1, t0 + step);

    int buf = 0;
    for (long long t = t0; t < fulltiles; t += step) {
        // Issue target loads BEFORE the async-copy wait: their DRAM latency
        // overlaps the wait window instead of following it.
        const float* trow = tgt + t * ROWS;
        float tv[ROWS / BLOCK];
        #pragma unroll
        for (int j = 0; j < ROWS / BLOCK; j++)
            tv[j] = __ldg(trow + tid + j * BLOCK);

        cp_wait<1>();        // current buffer's group complete
        __syncthreads();     // make its smem visible to all threads

        #pragma unroll
        for (int j = 0; j < ROWS / BLOCK; j++) {
            const int r = tid + j * BLOCK;
            const float x0 = s_in[buf][r * 5 + 0];
            const float x2 = s_in[buf][r * 5 + 2];
            const float x4 = s_in[buf][r * 5 + 4];
            const float d  = (fabsf(x4 - x2) < 0.1f) ? (x0 - x4) : (x0 - tv[j]);
            acc += fabsf(d);
        }

        __syncthreads();     // all threads done reading before refill
        stage(buf, t + 2 * step);
        buf ^= 1;
    }
    cp_wait<0>();            // drain remaining (possibly empty) groups
    __syncthreads();

    // Block reduction.
    #pragma unroll
    for (int off = 16; off > 0; off >>= 1)
        acc += __shfl_down_sync(0xFFFFFFFFu, acc, off);
    if ((tid & 31) == 0) s_red[tid >> 5] = acc;
    __syncthreads();

    __shared__ int s_last;
    if (tid == 0) {
        float v = 0.0f;
        #pragma unroll
        for (int w = 0; w < BLOCK / 32; w++) v += s_red[w];
        g_partials[blockIdx.x] = v;
        __threadfence();
        const unsigned int old = atomicAdd(&g_count, 1u);
        s_last = (old == gridDim.x - 1);
    }
    __syncthreads();

    // Last block to finish: deterministic double-precision final reduce.
    if (s_last) {
        double* sd = reinterpret_cast<double*>(&s_in[0][0]);  // 16B-aligned
        double a = 0.0;
        for (int i = tid; i < NBLOCKS; i += BLOCK)
            a += (double)g_partials[i];
        #pragma unroll
        for (int off = 16; off > 0; off >>= 1)
            a += __shfl_down_sync(0xFFFFFFFFu, a, off);
        if ((tid & 31) == 0) sd[tid >> 5] = a;
        __syncthreads();
        if (tid == 0) {
            double s = 0.0;
            #pragma unroll
            for (int w = 0; w < BLOCK / 32; w++) s += sd[w];
            out[0] = (float)(s / (double)nrows);
            g_count = 0;    // reset for next graph replay (determinism)
        }
    }
}

extern "C" void kernel_launch(void* const* d_in, const int* in_sizes, int n_in,
                              void* d_out, int out_size)
{
    const float* inputs  = (const float*)d_in[0];   // [N, 5] fp32
    const float* targets = (const float*)d_in[1];   // [N, 1] fp32
    float* out = (float*)d_out;

    const long long nrows = (long long)in_sizes[0] / 5;

    loss_kernel<<<NBLOCKS, BLOCK>>>(inputs, targets, nrows, out);
}